// round 13
// baseline (speedup 1.0000x reference)
#include <cuda_runtime.h>
#include <cuda_fp16.h>
#include <math.h>
#include <stdint.h>

// ---------------------------------------------------------------------------
// Problem constants
// ---------------------------------------------------------------------------
#define SS 2048
#define UU 1024
#define HD 128
#define NHEAD 32
#define MROWS 8192
#define LN_EPS 1e-8f
#define QSCALE 0.08838834764831845f        // 1/sqrt(128)
#define QSCALE_L2 0.12751743342040207f     // (1/sqrt(128)) * log2(e)

// ---------------------------------------------------------------------------
// Scratch (device globals; allocation-free rule)
// ---------------------------------------------------------------------------
__device__ __half g_xh[(size_t)MROWS * UU];
__device__ __half g_wth[4 * (size_t)UU * UU];      // W^T fp16, rows = 4096 outputs
__device__ __half g_qh[(size_t)MROWS * UU];
__device__ __half g_kh[(size_t)MROWS * UU];
__device__ __half g_vh[(size_t)MROWS * UU];
__device__ __half g_vt[(size_t)MROWS * UU];        // per-head V^T [d][s]
__device__ float  g_r[(size_t)MROWS * UU];
__device__ float  g_attn[(size_t)MROWS * UU];

// ---------------------------------------------------------------------------
// Helpers
// ---------------------------------------------------------------------------
__device__ __forceinline__ uint32_t smem_u32(const void* p) {
    uint32_t a;
    asm("{ .reg .u64 t; cvta.to.shared.u64 t, %1; cvt.u32.u64 %0, t; }" : "=r"(a) : "l"(p));
    return a;
}

#define CP_ASYNC16(sa, g) \
    asm volatile("cp.async.cg.shared.global [%0], [%1], 16;" :: "r"(sa), "l"(g))
#define CP_COMMIT() asm volatile("cp.async.commit_group;" ::: "memory")
#define CP_WAIT1()  asm volatile("cp.async.wait_group 1;" ::: "memory")

#define MMA_F16(d, a, b) \
    asm volatile("mma.sync.aligned.m16n8k16.row.col.f32.f16.f16.f32 " \
        "{%0,%1,%2,%3}, {%4,%5,%6,%7}, {%8,%9}, {%0,%1,%2,%3};" \
        : "+f"((d)[0]), "+f"((d)[1]), "+f"((d)[2]), "+f"((d)[3]) \
        : "r"((a)[0]), "r"((a)[1]), "r"((a)[2]), "r"((a)[3]), \
          "r"((b)[0]), "r"((b)[1]))

#define LDSM_X4(r0, r1, r2, r3, sa) \
    asm volatile("ldmatrix.sync.aligned.m8n8.x4.shared.b16 {%0,%1,%2,%3}, [%4];" \
        : "=r"(r0), "=r"(r1), "=r"(r2), "=r"(r3) : "r"(sa))

// pack two fp32 -> one half2 register (lo -> low half)
__device__ __forceinline__ uint32_t pack_h2(float lo, float hi) {
    uint32_t r;
    asm("cvt.rn.f16x2.f32 %0, %1, %2;" : "=r"(r) : "f"(hi), "f"(lo));
    return r;
}

// ---------------------------------------------------------------------------
// Fused projection GEMM (validated round 12): q|k|v|r = relu(x @ W + b).
// ---------------------------------------------------------------------------
#define HSTR 72
#define HROWB 144
#define HA_BYTES (128 * HROWB)
#define HSTAGE (2 * HA_BYTES)
#define HGSMEM (3 * HSTAGE)

__global__ __launch_bounds__(256, 2)
void gemm_proj(const __half* __restrict__ A, const __half* __restrict__ W,
               const float* __restrict__ bq, const float* __restrict__ bk,
               const float* __restrict__ bv, const float* __restrict__ brr,
               __half* __restrict__ qo, __half* __restrict__ ko,
               __half* __restrict__ vo, float* __restrict__ ro)
{
    extern __shared__ __align__(16) char hsm[];
    const uint32_t su = smem_u32(hsm);
    const int tid = threadIdx.x, lane = tid & 31, wid = tid >> 5;
    const int g = lane >> 2, c = lane & 3;
    const int wm0 = (wid >> 2) * 64, wn0 = (wid & 3) * 32;
    const int gm0 = blockIdx.y * 128;

    const __half* Ab = A + (size_t)gm0 * UU;
    const __half* Bb = W + (size_t)blockIdx.x * 128 * UU;

    const int lrow = lane & 7;
    const int axr = (lane >> 3) & 1, axc = lane >> 4;
    const int bxr = lane >> 4;

    uint32_t aOff[4], bOff[2];
#pragma unroll
    for (int mi = 0; mi < 4; mi++)
        aOff[mi] = (uint32_t)((wm0 + mi * 16 + axr * 8 + lrow) * HROWB + axc * 16);
#pragma unroll
    for (int np = 0; np < 2; np++)
        bOff[np] = (uint32_t)(HA_BYTES + (wn0 + np * 16 + bxr * 8 + lrow) * HROWB
                              + (((lane >> 3) & 1) * 16));

    float acc[4][4][4];
#pragma unroll
    for (int mi = 0; mi < 4; mi++)
#pragma unroll
        for (int ni = 0; ni < 4; ni++)
#pragma unroll
            for (int t = 0; t < 4; t++) acc[mi][ni][t] = 0.f;

    auto load_tile = [&](int i, int s) {
        const uint32_t abase = su + (uint32_t)(s * HSTAGE);
        const uint32_t bbase = abase + HA_BYTES;
#pragma unroll
        for (int it = 0; it < 4; it++) {
            int chunk = tid + it * 256;
            int row = chunk >> 3, ks = chunk & 7;
            CP_ASYNC16(abase + (uint32_t)(row * HROWB + ks * 16),
                       Ab + (size_t)row * UU + i * 64 + ks * 8);
        }
#pragma unroll
        for (int it = 0; it < 4; it++) {
            int chunk = tid + it * 256;
            int row = chunk >> 3, ks = chunk & 7;
            CP_ASYNC16(bbase + (uint32_t)(row * HROWB + ks * 16),
                       Bb + (size_t)row * UU + i * 64 + ks * 8);
        }
    };

    load_tile(0, 0); CP_COMMIT();
    load_tile(1, 1); CP_COMMIT();

    const int kIters = UU / 64;   // 16
    for (int i = 0; i < kIters; i++) {
        CP_WAIT1();
        __syncthreads();
        if (i + 2 < kIters) load_tile(i + 2, (i + 2) % 3);
        CP_COMMIT();

        const uint32_t sOff = su + (uint32_t)((i % 3) * HSTAGE);

#pragma unroll
        for (int j = 0; j < 4; j++) {
            uint32_t a[4][4], b[4][2];
#pragma unroll
            for (int mi = 0; mi < 4; mi++)
                LDSM_X4(a[mi][0], a[mi][1], a[mi][2], a[mi][3],
                        sOff + aOff[mi] + j * 32);
#pragma unroll
            for (int np = 0; np < 2; np++)
                LDSM_X4(b[2 * np][0], b[2 * np][1], b[2 * np + 1][0], b[2 * np + 1][1],
                        sOff + bOff[np] + j * 32);
#pragma unroll
            for (int mi = 0; mi < 4; mi++)
#pragma unroll
                for (int ni = 0; ni < 4; ni++)
                    MMA_F16(acc[mi][ni], a[mi], b[ni]);
        }
        __syncthreads();
    }

    // ---- epilogue: route to q/k/v (fp16) or r (fp32) ----
    const int which = blockIdx.x >> 3;                  // 0..3
    const int cbase = (blockIdx.x & 7) * 128 + wn0;
    const float scale = (which == 0) ? QSCALE_L2 : 1.0f;   // q pre-scaled for exp2 softmax
    const float* bp = (which == 0) ? bq : (which == 1) ? bk : (which == 2) ? bv : brr;
    __half* dsth = (which == 0) ? qo : (which == 1) ? ko : vo;

#pragma unroll
    for (int mi = 0; mi < 4; mi++) {
        const int r0 = gm0 + wm0 + mi * 16 + g;
#pragma unroll
        for (int ni = 0; ni < 4; ni++) {
            const int col = cbase + ni * 8 + c * 2;
            float b0 = __ldg(bp + col), b1 = __ldg(bp + col + 1);
            float v0 = fmaxf(acc[mi][ni][0] + b0, 0.f) * scale;
            float v1 = fmaxf(acc[mi][ni][1] + b1, 0.f) * scale;
            float v2 = fmaxf(acc[mi][ni][2] + b0, 0.f) * scale;
            float v3 = fmaxf(acc[mi][ni][3] + b1, 0.f) * scale;
            if (which < 3) {
                *(__half2*)(dsth + (size_t)r0 * UU + col) = __floats2half2_rn(v0, v1);
                *(__half2*)(dsth + (size_t)(r0 + 8) * UU + col) = __floats2half2_rn(v2, v3);
            } else {
                *(float2*)(ro + (size_t)r0 * UU + col) = make_float2(v0, v1);
                *(float2*)(ro + (size_t)(r0 + 8) * UU + col) = make_float2(v2, v3);
            }
        }
    }
}

// ---------------------------------------------------------------------------
// fp16 flash attention (round 12 layout). Softmax in exp2 domain (log2e
// folded into q scale); O-rescale skipped via warp vote when max unchanged.
// ---------------------------------------------------------------------------
#define FQB 128
#define FKB 64
#define FSTR 136
#define FROWB 272
#define FQ_BYTES (FQB * FROWB)                    // 34816
#define FK_BYTES (FKB * FROWB)                    // 17408
#define FV_BYTES (HD * HROWB)                     // 18432
#define FSTAGE (FK_BYTES + FV_BYTES)              // 35840
#define FL_SMEM (FQ_BYTES + 2 * FSTAGE)           // 106496

__global__ __launch_bounds__(256, 2)
void flash_h(const __half* __restrict__ q, const __half* __restrict__ k,
             const __half* __restrict__ vt, float* __restrict__ attn)
{
    extern __shared__ __align__(16) char fsm[];
    const uint32_t su = smem_u32(fsm);
    const int tid = threadIdx.x, lane = tid & 31, wid = tid >> 5;
    const int g = lane >> 2, c = lane & 3;
    const int h = blockIdx.y, qb = blockIdx.x;
    const int wq0 = wid * 16;

    const __half* qh = q + ((size_t)h * SS + (size_t)qb * FQB) * HD;
    const __half* kh = k + (size_t)h * SS * HD;
    const __half* vth = vt + (size_t)h * HD * SS;   // [d][s], ld = SS

    const int lrow = lane & 7;
    const int axr = (lane >> 3) & 1, axc = lane >> 4;
    const int bxc = (lane >> 3) & 1, bxr = lane >> 4;

    const uint32_t qAddr = su + (uint32_t)((wq0 + axr * 8 + lrow) * FROWB + axc * 16);
    const uint32_t kAddr = su + (uint32_t)(FQ_BYTES + (bxr * 8 + lrow) * FROWB + bxc * 16);
    const uint32_t vAddr = su + (uint32_t)(FQ_BYTES + FK_BYTES + (bxr * 8 + lrow) * HROWB + bxc * 16);

    // ---- stage Q ----
#pragma unroll
    for (int it = 0; it < 8; it++) {
        int idx = tid + it * 256;
        int row = idx >> 4, ks = idx & 15;
        CP_ASYNC16(su + (uint32_t)(row * FROWB + ks * 16),
                   qh + (size_t)row * HD + ks * 8);
    }
    CP_COMMIT();

    auto load_kv = [&](int i, int s) {
        const __half* kg = kh + (size_t)i * FKB * HD;
        const __half* vg = vth + (size_t)i * FKB;
        const uint32_t kbs = su + (uint32_t)(FQ_BYTES + s * FSTAGE);
        const uint32_t vbs = kbs + FK_BYTES;
#pragma unroll
        for (int it = 0; it < 4; it++) {
            int idx = tid + it * 256;
            int row = idx >> 4, ks = idx & 15;
            CP_ASYNC16(kbs + (uint32_t)(row * FROWB + ks * 16),
                       kg + (size_t)row * HD + ks * 8);
        }
#pragma unroll
        for (int it = 0; it < 4; it++) {
            int idx = tid + it * 256;
            int row = idx >> 3, ks = idx & 7;
            CP_ASYNC16(vbs + (uint32_t)(row * HROWB + ks * 16),
                       vg + (size_t)row * SS + ks * 8);
        }
    };
    load_kv(0, 0); CP_COMMIT();
    load_kv(1, 1); CP_COMMIT();

    float of[16][4];
#pragma unroll
    for (int ni = 0; ni < 16; ni++)
#pragma unroll
        for (int t = 0; t < 4; t++) of[ni][t] = 0.f;
    float rm[2] = {-1e30f, -1e30f};
    float rl[2] = {0.f, 0.f};

    const int nIter = SS / FKB;   // 32

#pragma unroll 1
    for (int i = 0; i < nIter; i++) {
        const uint32_t sOff = (uint32_t)((i & 1) * FSTAGE);
        CP_WAIT1();
        __syncthreads();

        // ---- S = Q @ K^T (logits already in log2 domain) ----
        float sacc[8][4];
#pragma unroll
        for (int ni = 0; ni < 8; ni++)
#pragma unroll
            for (int t = 0; t < 4; t++) sacc[ni][t] = 0.f;

#pragma unroll
        for (int j = 0; j < 8; j++) {
            uint32_t a[4], b[8][2];
            LDSM_X4(a[0], a[1], a[2], a[3], qAddr + j * 32);
#pragma unroll
            for (int np = 0; np < 4; np++)
                LDSM_X4(b[2 * np][0], b[2 * np][1], b[2 * np + 1][0], b[2 * np + 1][1],
                        kAddr + sOff + (uint32_t)(np * 16 * FROWB) + j * 32);
#pragma unroll
            for (int ni = 0; ni < 8; ni++)
                MMA_F16(sacc[ni], a, b[ni]);
        }

        // ---- online softmax in exp2 domain ----
        float alpha[2];
#pragma unroll
        for (int hf = 0; hf < 2; hf++) {
            float mx = -1e30f;
#pragma unroll
            for (int ni = 0; ni < 8; ni++) {
                mx = fmaxf(mx, sacc[ni][hf * 2]);
                mx = fmaxf(mx, sacc[ni][hf * 2 + 1]);
            }
            mx = fmaxf(mx, __shfl_xor_sync(0xffffffffu, mx, 1));
            mx = fmaxf(mx, __shfl_xor_sync(0xffffffffu, mx, 2));
            float mn = fmaxf(rm[hf], mx);
            alpha[hf] = exp2f(rm[hf] - mn);     // == 1.0 exactly when rm >= mx
            rm[hf] = mn;

            float rs = 0.f;
#pragma unroll
            for (int ni = 0; ni < 8; ni++) {
                float p0 = exp2f(sacc[ni][hf * 2]     - mn);
                float p1 = exp2f(sacc[ni][hf * 2 + 1] - mn);
                rs += p0 + p1;
                sacc[ni][hf * 2]     = p0;
                sacc[ni][hf * 2 + 1] = p1;
            }
            rs += __shfl_xor_sync(0xffffffffu, rs, 1);
            rs += __shfl_xor_sync(0xffffffffu, rs, 2);
            rl[hf] = rl[hf] * alpha[hf] + rs;
        }

        // ---- rescale O (warp-voted skip: max usually stabilizes early) ----
        if (!__all_sync(0xffffffffu, (alpha[0] == 1.f) && (alpha[1] == 1.f))) {
#pragma unroll
            for (int ni = 0; ni < 16; ni++) {
                of[ni][0] *= alpha[0];
                of[ni][1] *= alpha[0];
                of[ni][2] *= alpha[1];
                of[ni][3] *= alpha[1];
            }
        }

        // ---- O += P @ V ----
#pragma unroll
        for (int jj = 0; jj < 4; jj++) {
            uint32_t a[4];
            a[0] = pack_h2(sacc[2 * jj][0],     sacc[2 * jj][1]);
            a[1] = pack_h2(sacc[2 * jj][2],     sacc[2 * jj][3]);
            a[2] = pack_h2(sacc[2 * jj + 1][0], sacc[2 * jj + 1][1]);
            a[3] = pack_h2(sacc[2 * jj + 1][2], sacc[2 * jj + 1][3]);
#pragma unroll
            for (int np = 0; np < 8; np++) {
                uint32_t b0, b1, b2, b3;
                LDSM_X4(b0, b1, b2, b3,
                        vAddr + sOff + (uint32_t)(np * 16 * HROWB) + jj * 32);
                uint32_t bb0[2] = {b0, b1}, bb1[2] = {b2, b3};
                MMA_F16(of[2 * np], a, bb0);
                MMA_F16(of[2 * np + 1], a, bb1);
            }
        }

        __syncthreads();
        if (i + 2 < nIter) load_kv(i + 2, (i & 1));
        CP_COMMIT();
    }

    // ---- normalize + write ----
    float inv[2] = {1.0f / rl[0], 1.0f / rl[1]};
    float* outb = attn + ((size_t)h * SS + (size_t)qb * FQB + wq0) * HD;
#pragma unroll
    for (int hf = 0; hf < 2; hf++) {
        float* rowp = outb + (size_t)(hf * 8 + g) * HD;
#pragma unroll
        for (int ni = 0; ni < 16; ni++)
            *(float2*)(rowp + ni * 8 + 2 * c) =
                make_float2(of[ni][hf * 2] * inv[hf], of[ni][hf * 2 + 1] * inv[hf]);
    }
}

// ---------------------------------------------------------------------------
// Prep kernels
// ---------------------------------------------------------------------------
__global__ __launch_bounds__(256)
void cvtx_kernel(const float* __restrict__ in, __half* __restrict__ out, int n4)
{
    int i = blockIdx.x * 256 + threadIdx.x;
    if (i < n4) {
        float4 v = ((const float4*)in)[i];
        ((__half2*)out)[2 * i]     = __floats2half2_rn(v.x, v.y);
        ((__half2*)out)[2 * i + 1] = __floats2half2_rn(v.z, v.w);
    }
}

__global__ __launch_bounds__(256)
void cvtWT_all(const float* __restrict__ W0, const float* __restrict__ W1,
               const float* __restrict__ W2, const float* __restrict__ W3,
               __half* __restrict__ out)
{
    __shared__ float t[32][33];
    const int z = blockIdx.z;
    const float* in = (z == 0) ? W0 : (z == 1) ? W1 : (z == 2) ? W2 : W3;
    __half* o = out + (size_t)z * UU * UU;
    int k0 = blockIdx.y * 32, n0 = blockIdx.x * 32;
    int tx = threadIdx.x & 31, ty = threadIdx.x >> 5;
#pragma unroll
    for (int r = 0; r < 32; r += 8)
        t[ty + r][tx] = in[(size_t)(k0 + ty + r) * UU + n0 + tx];
    __syncthreads();
#pragma unroll
    for (int r = 0; r < 32; r += 8)
        o[(size_t)(n0 + ty + r) * UU + k0 + tx] = __float2half_rn(t[tx][ty + r]);
}

__global__ __launch_bounds__(256)
void transposeV_kernel(const __half* __restrict__ v, __half* __restrict__ vt)
{   // per head h (raw-reshape contiguous view): vt[h][d][s] = v[h][s][d]
    __shared__ __half t[32][40];
    int h = blockIdx.z;
    int d0 = blockIdx.x * 32, s0 = blockIdx.y * 32;
    const __half* vh = v + (size_t)h * SS * HD;
    __half* vth = vt + (size_t)h * HD * SS;
    int tx = threadIdx.x & 31, ty = threadIdx.x >> 5;
#pragma unroll
    for (int r = 0; r < 32; r += 8)
        t[ty + r][tx] = vh[(size_t)(s0 + ty + r) * HD + d0 + tx];
    __syncthreads();
#pragma unroll
    for (int r = 0; r < 32; r += 8)
        vth[(size_t)(d0 + ty + r) * SS + s0 + tx] = t[tx][ty + r];
}

// ---------------------------------------------------------------------------
// Fused epilogue: out = gamma * LN(relu(attn + res)) + beta
// ---------------------------------------------------------------------------
__device__ __forceinline__ float block_sum_256(float v, float* sh)
{
#pragma unroll
    for (int o = 16; o > 0; o >>= 1) v += __shfl_xor_sync(0xffffffffu, v, o);
    if ((threadIdx.x & 31) == 0) sh[threadIdx.x >> 5] = v;
    __syncthreads();
    float t = 0.f;
#pragma unroll
    for (int i = 0; i < 8; i++) t += sh[i];
    __syncthreads();
    return t;
}

__global__ __launch_bounds__(256)
void ln_kernel(const float* __restrict__ attn, const float* __restrict__ res,
               const float* __restrict__ gamma, const float* __restrict__ beta,
               float* __restrict__ out)
{
    __shared__ float sh[8];
    const int tid = threadIdx.x;
    const size_t base = (size_t)blockIdx.x * UU;

    float v[4];
    float s = 0.f;
#pragma unroll
    for (int i = 0; i < 4; i++) {
        int cidx = tid + i * 256;
        float t = fmaxf(attn[base + cidx] + res[base + cidx], 0.f);
        v[i] = t; s += t;
    }
    const float mean = block_sum_256(s, sh) * (1.0f / UU);

    float vs = 0.f;
#pragma unroll
    for (int i = 0; i < 4; i++) { float d = v[i] - mean; vs += d * d; }
    const float var = block_sum_256(vs, sh) * (1.0f / UU);
    const float inv = rsqrtf(var + LN_EPS);

#pragma unroll
    for (int i = 0; i < 4; i++) {
        int cidx = tid + i * 256;
        out[base + cidx] = gamma[cidx] * ((v[i] - mean) * inv) + beta[cidx];
    }
}

// ---------------------------------------------------------------------------
extern "C" void kernel_launch(void* const* d_in, const int* in_sizes, int n_in,
                              void* d_out, int out_size)
{
    const float* x     = (const float*)d_in[0];
    const float* Wq    = (const float*)d_in[1];
    const float* bq    = (const float*)d_in[2];
    const float* Wk    = (const float*)d_in[3];
    const float* bk    = (const float*)d_in[4];
    const float* Wv    = (const float*)d_in[5];
    const float* bv    = (const float*)d_in[6];
    const float* Wr    = (const float*)d_in[7];
    const float* br_   = (const float*)d_in[8];
    const float* gamma = (const float*)d_in[9];
    const float* beta  = (const float*)d_in[10];
    float* out = (float*)d_out;

    __half *xh, *wth, *qh, *kh, *vh, *vt;
    float *r, *attn;
    cudaGetSymbolAddress((void**)&xh,   g_xh);
    cudaGetSymbolAddress((void**)&wth,  g_wth);
    cudaGetSymbolAddress((void**)&qh,   g_qh);
    cudaGetSymbolAddress((void**)&kh,   g_kh);
    cudaGetSymbolAddress((void**)&vh,   g_vh);
    cudaGetSymbolAddress((void**)&vt,   g_vt);
    cudaGetSymbolAddress((void**)&r,    g_r);
    cudaGetSymbolAddress((void**)&attn, g_attn);

    cudaFuncSetAttribute(gemm_proj, cudaFuncAttributeMaxDynamicSharedMemorySize, HGSMEM);
    cudaFuncSetAttribute(flash_h,   cudaFuncAttributeMaxDynamicSharedMemorySize, FL_SMEM);

    // 1) fp16 conversions
    cvtx_kernel<<<(MROWS * UU / 4 + 255) / 256, 256>>>(x, xh, MROWS * UU / 4);
    cvtWT_all<<<dim3(UU / 32, UU / 32, 4), 256>>>(Wq, Wk, Wv, Wr, wth);

    // 2) fused projections (q|k|v|r in one launch; q scaled by log2e/sqrt(HD))
    gemm_proj<<<dim3(4 * UU / 128, MROWS / 128), 256, HGSMEM>>>(
        xh, wth, bq, bk, bv, br_, qh, kh, vh, r);

    // 3) per-head V^T
    transposeV_kernel<<<dim3(HD / 32, SS / 32, NHEAD), 256>>>(vh, vt);

    // 4) fused flash attention (exp2-domain softmax)
    flash_h<<<dim3(SS / FQB, NHEAD), 256, FL_SMEM>>>(qh, kh, vt, attn);

    // 5) LayerNorm epilogue
    ln_kernel<<<MROWS, 256>>>(attn, r, gamma, beta, out);
}

// round 14
// speedup vs baseline: 1.0283x; 1.0283x over previous
#include <cuda_runtime.h>
#include <cuda_fp16.h>
#include <math.h>
#include <stdint.h>

// ---------------------------------------------------------------------------
// Problem constants
// ---------------------------------------------------------------------------
#define SS 2048
#define UU 1024
#define HD 128
#define NHEAD 32
#define MROWS 8192
#define LN_EPS 1e-8f
#define QSCALE 0.08838834764831845f   // 1/sqrt(128)

// ---------------------------------------------------------------------------
// Scratch (device globals; allocation-free rule)
// ---------------------------------------------------------------------------
__device__ __half g_xh[(size_t)MROWS * UU];
__device__ __half g_wth[4 * (size_t)UU * UU];      // W^T fp16, rows = 4096 outputs
__device__ __half g_qh[(size_t)MROWS * UU];
__device__ __half g_kh[(size_t)MROWS * UU];
__device__ __half g_vh[(size_t)MROWS * UU];
__device__ __half g_vt[(size_t)MROWS * UU];        // per-head V^T [d][s]
__device__ float  g_r[(size_t)MROWS * UU];

// ---------------------------------------------------------------------------
// Helpers
// ---------------------------------------------------------------------------
__device__ __forceinline__ uint32_t smem_u32(const void* p) {
    uint32_t a;
    asm("{ .reg .u64 t; cvta.to.shared.u64 t, %1; cvt.u32.u64 %0, t; }" : "=r"(a) : "l"(p));
    return a;
}

#define CP_ASYNC16(sa, g) \
    asm volatile("cp.async.cg.shared.global [%0], [%1], 16;" :: "r"(sa), "l"(g))
#define CP_COMMIT() asm volatile("cp.async.commit_group;" ::: "memory")
#define CP_WAIT1()  asm volatile("cp.async.wait_group 1;" ::: "memory")

#define MMA_F16(d, a, b) \
    asm volatile("mma.sync.aligned.m16n8k16.row.col.f32.f16.f16.f32 " \
        "{%0,%1,%2,%3}, {%4,%5,%6,%7}, {%8,%9}, {%0,%1,%2,%3};" \
        : "+f"((d)[0]), "+f"((d)[1]), "+f"((d)[2]), "+f"((d)[3]) \
        : "r"((a)[0]), "r"((a)[1]), "r"((a)[2]), "r"((a)[3]), \
          "r"((b)[0]), "r"((b)[1]))

#define LDSM_X4(r0, r1, r2, r3, sa) \
    asm volatile("ldmatrix.sync.aligned.m8n8.x4.shared.b16 {%0,%1,%2,%3}, [%4];" \
        : "=r"(r0), "=r"(r1), "=r"(r2), "=r"(r3) : "r"(sa))

// pack two fp32 -> one half2 register (lo -> low half)
__device__ __forceinline__ uint32_t pack_h2(float lo, float hi) {
    uint32_t r;
    asm("cvt.rn.f16x2.f32 %0, %1, %2;" : "=r"(r) : "f"(hi), "f"(lo));
    return r;
}

// ---------------------------------------------------------------------------
// Fused projection GEMM (validated round 12): q|k|v|r = relu(x @ W + b).
// 256 threads = 8 warps (2x4), warp tile 64x32, BK=64, 3-stage cp.async.
// ---------------------------------------------------------------------------
#define HSTR 72
#define HROWB 144
#define HA_BYTES (128 * HROWB)
#define HSTAGE (2 * HA_BYTES)
#define HGSMEM (3 * HSTAGE)

__global__ __launch_bounds__(256, 2)
void gemm_proj(const __half* __restrict__ A, const __half* __restrict__ W,
               const float* __restrict__ bq, const float* __restrict__ bk,
               const float* __restrict__ bv, const float* __restrict__ brr,
               __half* __restrict__ qo, __half* __restrict__ ko,
               __half* __restrict__ vo, float* __restrict__ ro)
{
    extern __shared__ __align__(16) char hsm[];
    const uint32_t su = smem_u32(hsm);
    const int tid = threadIdx.x, lane = tid & 31, wid = tid >> 5;
    const int g = lane >> 2, c = lane & 3;
    const int wm0 = (wid >> 2) * 64, wn0 = (wid & 3) * 32;
    const int gm0 = blockIdx.y * 128;

    const __half* Ab = A + (size_t)gm0 * UU;
    const __half* Bb = W + (size_t)blockIdx.x * 128 * UU;

    const int lrow = lane & 7;
    const int axr = (lane >> 3) & 1, axc = lane >> 4;
    const int bxr = lane >> 4;

    uint32_t aOff[4], bOff[2];
#pragma unroll
    for (int mi = 0; mi < 4; mi++)
        aOff[mi] = (uint32_t)((wm0 + mi * 16 + axr * 8 + lrow) * HROWB + axc * 16);
#pragma unroll
    for (int np = 0; np < 2; np++)
        bOff[np] = (uint32_t)(HA_BYTES + (wn0 + np * 16 + bxr * 8 + lrow) * HROWB
                              + (((lane >> 3) & 1) * 16));

    float acc[4][4][4];
#pragma unroll
    for (int mi = 0; mi < 4; mi++)
#pragma unroll
        for (int ni = 0; ni < 4; ni++)
#pragma unroll
            for (int t = 0; t < 4; t++) acc[mi][ni][t] = 0.f;

    auto load_tile = [&](int i, int s) {
        const uint32_t abase = su + (uint32_t)(s * HSTAGE);
        const uint32_t bbase = abase + HA_BYTES;
#pragma unroll
        for (int it = 0; it < 4; it++) {
            int chunk = tid + it * 256;
            int row = chunk >> 3, ks = chunk & 7;
            CP_ASYNC16(abase + (uint32_t)(row * HROWB + ks * 16),
                       Ab + (size_t)row * UU + i * 64 + ks * 8);
        }
#pragma unroll
        for (int it = 0; it < 4; it++) {
            int chunk = tid + it * 256;
            int row = chunk >> 3, ks = chunk & 7;
            CP_ASYNC16(bbase + (uint32_t)(row * HROWB + ks * 16),
                       Bb + (size_t)row * UU + i * 64 + ks * 8);
        }
    };

    load_tile(0, 0); CP_COMMIT();
    load_tile(1, 1); CP_COMMIT();

    const int kIters = UU / 64;   // 16
    for (int i = 0; i < kIters; i++) {
        CP_WAIT1();
        __syncthreads();
        if (i + 2 < kIters) load_tile(i + 2, (i + 2) % 3);
        CP_COMMIT();

        const uint32_t sOff = su + (uint32_t)((i % 3) * HSTAGE);

#pragma unroll
        for (int j = 0; j < 4; j++) {
            uint32_t a[4][4], b[4][2];
#pragma unroll
            for (int mi = 0; mi < 4; mi++)
                LDSM_X4(a[mi][0], a[mi][1], a[mi][2], a[mi][3],
                        sOff + aOff[mi] + j * 32);
#pragma unroll
            for (int np = 0; np < 2; np++)
                LDSM_X4(b[2 * np][0], b[2 * np][1], b[2 * np + 1][0], b[2 * np + 1][1],
                        sOff + bOff[np] + j * 32);
#pragma unroll
            for (int mi = 0; mi < 4; mi++)
#pragma unroll
                for (int ni = 0; ni < 4; ni++)
                    MMA_F16(acc[mi][ni], a[mi], b[ni]);
        }
        __syncthreads();
    }

    // ---- epilogue: route to q/k/v (fp16) or r (fp32) ----
    const int which = blockIdx.x >> 3;                  // 0..3
    const int cbase = (blockIdx.x & 7) * 128 + wn0;
    const float scale = (which == 0) ? QSCALE : 1.0f;
    const float* bp = (which == 0) ? bq : (which == 1) ? bk : (which == 2) ? bv : brr;
    __half* dsth = (which == 0) ? qo : (which == 1) ? ko : vo;

#pragma unroll
    for (int mi = 0; mi < 4; mi++) {
        const int r0 = gm0 + wm0 + mi * 16 + g;
#pragma unroll
        for (int ni = 0; ni < 4; ni++) {
            const int col = cbase + ni * 8 + c * 2;
            float b0 = __ldg(bp + col), b1 = __ldg(bp + col + 1);
            float v0 = fmaxf(acc[mi][ni][0] + b0, 0.f) * scale;
            float v1 = fmaxf(acc[mi][ni][1] + b1, 0.f) * scale;
            float v2 = fmaxf(acc[mi][ni][2] + b0, 0.f) * scale;
            float v3 = fmaxf(acc[mi][ni][3] + b1, 0.f) * scale;
            if (which < 3) {
                *(__half2*)(dsth + (size_t)r0 * UU + col) = __floats2half2_rn(v0, v1);
                *(__half2*)(dsth + (size_t)(r0 + 8) * UU + col) = __floats2half2_rn(v2, v3);
            } else {
                *(float2*)(ro + (size_t)r0 * UU + col) = make_float2(v0, v1);
                *(float2*)(ro + (size_t)(r0 + 8) * UU + col) = make_float2(v2, v3);
            }
        }
    }
}

// ---------------------------------------------------------------------------
// fp16 flash attention (round 12 core) + FUSED LayerNorm epilogue.
// Raw-reshape algebra: one LN row (1024) = 8 consecutive s x 128 d of one
// head; a warp's 16 s-rows = exactly 2 LN rows; for fixed hf the 32 lanes
// hold the complete 8x128 row set -> full-warp shuffle reductions.
// out = gamma * LN(relu(attn + r)) + beta written directly; no attn buffer.
// ---------------------------------------------------------------------------
#define FQB 128
#define FKB 64
#define FROWB 272
#define FQ_BYTES (FQB * FROWB)                    // 34816
#define FK_BYTES (FKB * FROWB)                    // 17408
#define FV_BYTES (HD * HROWB)                     // 18432
#define FSTAGE (FK_BYTES + FV_BYTES)              // 35840
#define FL_SMEM (FQ_BYTES + 2 * FSTAGE)           // 106496

__global__ __launch_bounds__(256, 2)
void flash_h(const __half* __restrict__ q, const __half* __restrict__ k,
             const __half* __restrict__ vt, const float* __restrict__ res,
             const float* __restrict__ gamma, const float* __restrict__ beta,
             float* __restrict__ out)
{
    extern __shared__ __align__(16) char fsm[];
    const uint32_t su = smem_u32(fsm);
    const int tid = threadIdx.x, lane = tid & 31, wid = tid >> 5;
    const int g = lane >> 2, c = lane & 3;
    const int h = blockIdx.y, qb = blockIdx.x;
    const int wq0 = wid * 16;

    const __half* qh = q + ((size_t)h * SS + (size_t)qb * FQB) * HD;
    const __half* kh = k + (size_t)h * SS * HD;
    const __half* vth = vt + (size_t)h * HD * SS;   // [d][s], ld = SS

    const int lrow = lane & 7;
    const int axr = (lane >> 3) & 1, axc = lane >> 4;
    const int bxc = (lane >> 3) & 1, bxr = lane >> 4;

    const uint32_t qAddr = su + (uint32_t)((wq0 + axr * 8 + lrow) * FROWB + axc * 16);
    const uint32_t kAddr = su + (uint32_t)(FQ_BYTES + (bxr * 8 + lrow) * FROWB + bxc * 16);
    const uint32_t vAddr = su + (uint32_t)(FQ_BYTES + FK_BYTES + (bxr * 8 + lrow) * HROWB + bxc * 16);

    // ---- stage Q ----
#pragma unroll
    for (int it = 0; it < 8; it++) {
        int idx = tid + it * 256;
        int row = idx >> 4, ks = idx & 15;
        CP_ASYNC16(su + (uint32_t)(row * FROWB + ks * 16),
                   qh + (size_t)row * HD + ks * 8);
    }
    CP_COMMIT();

    auto load_kv = [&](int i, int s) {
        const __half* kg = kh + (size_t)i * FKB * HD;
        const __half* vg = vth + (size_t)i * FKB;
        const uint32_t kbs = su + (uint32_t)(FQ_BYTES + s * FSTAGE);
        const uint32_t vbs = kbs + FK_BYTES;
#pragma unroll
        for (int it = 0; it < 4; it++) {
            int idx = tid + it * 256;
            int row = idx >> 4, ks = idx & 15;
            CP_ASYNC16(kbs + (uint32_t)(row * FROWB + ks * 16),
                       kg + (size_t)row * HD + ks * 8);
        }
#pragma unroll
        for (int it = 0; it < 4; it++) {
            int idx = tid + it * 256;
            int row = idx >> 3, ks = idx & 7;
            CP_ASYNC16(vbs + (uint32_t)(row * HROWB + ks * 16),
                       vg + (size_t)row * SS + ks * 8);
        }
    };
    load_kv(0, 0); CP_COMMIT();
    load_kv(1, 1); CP_COMMIT();

    float of[16][4];
#pragma unroll
    for (int ni = 0; ni < 16; ni++)
#pragma unroll
        for (int t = 0; t < 4; t++) of[ni][t] = 0.f;
    float rm[2] = {-1e30f, -1e30f};
    float rl[2] = {0.f, 0.f};

    const int nIter = SS / FKB;   // 32

#pragma unroll 1
    for (int i = 0; i < nIter; i++) {
        const uint32_t sOff = (uint32_t)((i & 1) * FSTAGE);
        CP_WAIT1();
        __syncthreads();

        // ---- S = Q @ K^T ----
        float sacc[8][4];
#pragma unroll
        for (int ni = 0; ni < 8; ni++)
#pragma unroll
            for (int t = 0; t < 4; t++) sacc[ni][t] = 0.f;

#pragma unroll
        for (int j = 0; j < 8; j++) {
            uint32_t a[4], b[8][2];
            LDSM_X4(a[0], a[1], a[2], a[3], qAddr + j * 32);
#pragma unroll
            for (int np = 0; np < 4; np++)
                LDSM_X4(b[2 * np][0], b[2 * np][1], b[2 * np + 1][0], b[2 * np + 1][1],
                        kAddr + sOff + (uint32_t)(np * 16 * FROWB) + j * 32);
#pragma unroll
            for (int ni = 0; ni < 8; ni++)
                MMA_F16(sacc[ni], a, b[ni]);
        }

        // ---- online softmax ----
        float alpha[2];
#pragma unroll
        for (int hf = 0; hf < 2; hf++) {
            float mx = -1e30f;
#pragma unroll
            for (int ni = 0; ni < 8; ni++) {
                mx = fmaxf(mx, sacc[ni][hf * 2]);
                mx = fmaxf(mx, sacc[ni][hf * 2 + 1]);
            }
            mx = fmaxf(mx, __shfl_xor_sync(0xffffffffu, mx, 1));
            mx = fmaxf(mx, __shfl_xor_sync(0xffffffffu, mx, 2));
            float mn = fmaxf(rm[hf], mx);
            alpha[hf] = __expf(rm[hf] - mn);
            rm[hf] = mn;

            float rs = 0.f;
#pragma unroll
            for (int ni = 0; ni < 8; ni++) {
                float p0 = __expf(sacc[ni][hf * 2]     - mn);
                float p1 = __expf(sacc[ni][hf * 2 + 1] - mn);
                rs += p0 + p1;
                sacc[ni][hf * 2]     = p0;
                sacc[ni][hf * 2 + 1] = p1;
            }
            rs += __shfl_xor_sync(0xffffffffu, rs, 1);
            rs += __shfl_xor_sync(0xffffffffu, rs, 2);
            rl[hf] = rl[hf] * alpha[hf] + rs;
        }

        // ---- rescale O ----
#pragma unroll
        for (int ni = 0; ni < 16; ni++) {
            of[ni][0] *= alpha[0];
            of[ni][1] *= alpha[0];
            of[ni][2] *= alpha[1];
            of[ni][3] *= alpha[1];
        }

        // ---- O += P @ V ----
#pragma unroll
        for (int jj = 0; jj < 4; jj++) {
            uint32_t a[4];
            a[0] = pack_h2(sacc[2 * jj][0],     sacc[2 * jj][1]);
            a[1] = pack_h2(sacc[2 * jj][2],     sacc[2 * jj][3]);
            a[2] = pack_h2(sacc[2 * jj + 1][0], sacc[2 * jj + 1][1]);
            a[3] = pack_h2(sacc[2 * jj + 1][2], sacc[2 * jj + 1][3]);
#pragma unroll
            for (int np = 0; np < 8; np++) {
                uint32_t b0, b1, b2, b3;
                LDSM_X4(b0, b1, b2, b3,
                        vAddr + sOff + (uint32_t)(np * 16 * HROWB) + jj * 32);
                uint32_t bb0[2] = {b0, b1}, bb1[2] = {b2, b3};
                MMA_F16(of[2 * np], a, bb0);
                MMA_F16(of[2 * np + 1], a, bb1);
            }
        }

        __syncthreads();
        if (i + 2 < nIter) load_kv(i + 2, (i & 1));
        CP_COMMIT();
    }

    // ---- fused epilogue: softmax-normalize, +res, relu, LayerNorm, write ----
    const float inv[2] = {1.0f / rl[0], 1.0f / rl[1]};
    const size_t rowbase = (size_t)h * SS + (size_t)qb * FQB + wq0;

#pragma unroll
    for (int hf = 0; hf < 2; hf++) {
        const size_t gr = rowbase + hf * 8 + g;       // global s-row; gr & 7 == g
        const float* rrow = res + gr * HD;

        // t = relu(o * inv + r), stored back into of[][hf*2 ..]; warp sum
        float s = 0.f;
#pragma unroll
        for (int ni = 0; ni < 16; ni++) {
            float2 rv = *(const float2*)(rrow + ni * 8 + 2 * c);
            float t0 = fmaxf(of[ni][hf * 2]     * inv[hf] + rv.x, 0.f);
            float t1 = fmaxf(of[ni][hf * 2 + 1] * inv[hf] + rv.y, 0.f);
            of[ni][hf * 2]     = t0;
            of[ni][hf * 2 + 1] = t1;
            s += t0 + t1;
        }
#pragma unroll
        for (int o = 16; o > 0; o >>= 1) s += __shfl_xor_sync(0xffffffffu, s, o);
        const float mean = s * (1.0f / UU);

        float vs = 0.f;
#pragma unroll
        for (int ni = 0; ni < 16; ni++) {
            float d0 = of[ni][hf * 2]     - mean;
            float d1 = of[ni][hf * 2 + 1] - mean;
            vs += d0 * d0 + d1 * d1;
        }
#pragma unroll
        for (int o = 16; o > 0; o >>= 1) vs += __shfl_xor_sync(0xffffffffu, vs, o);
        const float rinv = rsqrtf(vs * (1.0f / UU) + LN_EPS);

        float* orow = out + gr * HD;
#pragma unroll
        for (int ni = 0; ni < 16; ni++) {
            const int col = g * 128 + ni * 8 + 2 * c;  // LN column
            float g0 = __ldg(gamma + col), g1 = __ldg(gamma + col + 1);
            float be0 = __ldg(beta + col), be1 = __ldg(beta + col + 1);
            float o0 = g0 * (of[ni][hf * 2]     - mean) * rinv + be0;
            float o1 = g1 * (of[ni][hf * 2 + 1] - mean) * rinv + be1;
            *(float2*)(orow + ni * 8 + 2 * c) = make_float2(o0, o1);
        }
    }
}

// ---------------------------------------------------------------------------
// Prep kernels
// ---------------------------------------------------------------------------
__global__ __launch_bounds__(256)
void cvtx_kernel(const float* __restrict__ in, __half* __restrict__ out, int n4)
{
    int i = blockIdx.x * 256 + threadIdx.x;
    if (i < n4) {
        float4 v = ((const float4*)in)[i];
        ((__half2*)out)[2 * i]     = __floats2half2_rn(v.x, v.y);
        ((__half2*)out)[2 * i + 1] = __floats2half2_rn(v.z, v.w);
    }
}

__global__ __launch_bounds__(256)
void cvtWT_all(const float* __restrict__ W0, const float* __restrict__ W1,
               const float* __restrict__ W2, const float* __restrict__ W3,
               __half* __restrict__ out)
{
    __shared__ float t[32][33];
    const int z = blockIdx.z;
    const float* in = (z == 0) ? W0 : (z == 1) ? W1 : (z == 2) ? W2 : W3;
    __half* o = out + (size_t)z * UU * UU;
    int k0 = blockIdx.y * 32, n0 = blockIdx.x * 32;
    int tx = threadIdx.x & 31, ty = threadIdx.x >> 5;
#pragma unroll
    for (int r = 0; r < 32; r += 8)
        t[ty + r][tx] = in[(size_t)(k0 + ty + r) * UU + n0 + tx];
    __syncthreads();
#pragma unroll
    for (int r = 0; r < 32; r += 8)
        o[(size_t)(n0 + ty + r) * UU + k0 + tx] = __float2half_rn(t[tx][ty + r]);
}

__global__ __launch_bounds__(256)
void transposeV_kernel(const __half* __restrict__ v, __half* __restrict__ vt)
{   // per head h (raw-reshape contiguous view): vt[h][d][s] = v[h][s][d]
    __shared__ float t[32][33];
    int h = blockIdx.z;
    int d0 = blockIdx.x * 32, s0 = blockIdx.y * 32;
    const __half* vh = v + (size_t)h * SS * HD;
    __half* vth = vt + (size_t)h * HD * SS;
    int tx = threadIdx.x & 31, ty = threadIdx.x >> 5;
#pragma unroll
    for (int r = 0; r < 32; r += 8)
        t[ty + r][tx] = __half2float(vh[(size_t)(s0 + ty + r) * HD + d0 + tx]);
    __syncthreads();
#pragma unroll
    for (int r = 0; r < 32; r += 8)
        vth[(size_t)(d0 + ty + r) * SS + s0 + tx] = __float2half_rn(t[tx][ty + r]);
}

// ---------------------------------------------------------------------------
extern "C" void kernel_launch(void* const* d_in, const int* in_sizes, int n_in,
                              void* d_out, int out_size)
{
    const float* x     = (const float*)d_in[0];
    const float* Wq    = (const float*)d_in[1];
    const float* bq    = (const float*)d_in[2];
    const float* Wk    = (const float*)d_in[3];
    const float* bk    = (const float*)d_in[4];
    const float* Wv    = (const float*)d_in[5];
    const float* bv    = (const float*)d_in[6];
    const float* Wr    = (const float*)d_in[7];
    const float* br_   = (const float*)d_in[8];
    const float* gamma = (const float*)d_in[9];
    const float* beta  = (const float*)d_in[10];
    float* out = (float*)d_out;

    __half *xh, *wth, *qh, *kh, *vh, *vt;
    float *r;
    cudaGetSymbolAddress((void**)&xh,   g_xh);
    cudaGetSymbolAddress((void**)&wth,  g_wth);
    cudaGetSymbolAddress((void**)&qh,   g_qh);
    cudaGetSymbolAddress((void**)&kh,   g_kh);
    cudaGetSymbolAddress((void**)&vh,   g_vh);
    cudaGetSymbolAddress((void**)&vt,   g_vt);
    cudaGetSymbolAddress((void**)&r,    g_r);

    cudaFuncSetAttribute(gemm_proj, cudaFuncAttributeMaxDynamicSharedMemorySize, HGSMEM);
    cudaFuncSetAttribute(flash_h,   cudaFuncAttributeMaxDynamicSharedMemorySize, FL_SMEM);

    // 1) fp16 conversions
    cvtx_kernel<<<(MROWS * UU / 4 + 255) / 256, 256>>>(x, xh, MROWS * UU / 4);
    cvtWT_all<<<dim3(UU / 32, UU / 32, 4), 256>>>(Wq, Wk, Wv, Wr, wth);

    // 2) fused projections (q|k|v|r in one launch)
    gemm_proj<<<dim3(4 * UU / 128, MROWS / 128), 256, HGSMEM>>>(
        xh, wth, bq, bk, bv, br_, qh, kh, vh, r);

    // 3) per-head V^T
    transposeV_kernel<<<dim3(HD / 32, SS / 32, NHEAD), 256>>>(vh, vt);

    // 4) fused flash attention + residual + ReLU + LayerNorm (writes d_out)
    flash_h<<<dim3(SS / FQB, NHEAD), 256, FL_SMEM>>>(qh, kh, vt, r, gamma, beta, out);
}